// round 14
// baseline (speedup 1.0000x reference)
#include <cuda_runtime.h>
#include <cuda_bf16.h>
#include <math.h>

// ---------------- problem constants ----------------
#define NB   16          // batch
#define LSEQ 256         // sequence length (TY+1)
#define ENC  512
#define EMB  256
#define DEC  512
#define NV   32000
#define G4   2048        // 4*DEC
#define MROWS 4096       // NB*LSEQ

// ---------------- scratch (__device__ globals; no allocs) ----------------
__device__ float g_seq [NB*LSEQ*EMB];        //  4 MB  [b][t][EMB]
__device__ float g_xw  [LSEQ*G4*NB];         // 32 MB  [t][j][b]
__device__ float g_cat [NB*LSEQ*2*DEC];      // 16 MB  [b][t][ mix(512) | h1(512) ]
__device__ float g_attn[MROWS*DEC];          //  8 MB  [m][512]
__device__ float g_h2  [MROWS*DEC];          //  8 MB  [m][512]
// packed bf16 hi/lo h ring in fragment layout: [slot][plane][b][dp] (u32)
__device__ unsigned g_hP[2*2*16*256];        // 64 KB
// barrier state (monotonic gen; leaf/root self-reset)
__device__ unsigned g_leaf[16*32];           // 16 counters, 128B apart
__device__ unsigned g_root;
__device__ unsigned g_genv;

__device__ __forceinline__ float sigf(float x){ return 1.0f/(1.0f+__expf(-x)); }

// ---------------- acquire/release primitives ----------------
__device__ __forceinline__ unsigned atom_add_rel(unsigned* p, unsigned v){
    unsigned old;
    asm volatile("atom.release.gpu.global.add.u32 %0, [%1], %2;"
                 : "=r"(old) : "l"(p), "r"(v) : "memory");
    return old;
}
__device__ __forceinline__ void red_add_rel(unsigned* p, unsigned v){
    asm volatile("red.release.gpu.global.add.u32 [%0], %1;"
                 :: "l"(p), "r"(v) : "memory");
}
__device__ __forceinline__ unsigned ld_acq(const unsigned* p){
    unsigned v;
    asm volatile("ld.acquire.gpu.global.u32 %0, [%1];" : "=r"(v) : "l"(p) : "memory");
    return v;
}
__device__ __forceinline__ void st_rlx(unsigned* p, unsigned v){
    asm volatile("st.relaxed.gpu.global.u32 [%0], %1;" :: "l"(p), "r"(v) : "memory");
}
__device__ __forceinline__ void st_cg_u32(unsigned* p, unsigned v){
    asm volatile("st.global.cg.u32 [%0], %1;" :: "l"(p), "r"(v) : "memory");
}

// tid0 arrival (call after intra-CTA ordering is established)
__device__ __forceinline__ void bar_arrive(int cta){
    unsigned leaf = (unsigned)cta & 15u;
    if (atom_add_rel(&g_leaf[leaf*32], 1u) == 7u) {
        st_rlx(&g_leaf[leaf*32], 0u);
        if (atom_add_rel(&g_root, 1u) == 15u) {
            st_rlx(&g_root, 0u);
            red_add_rel(&g_genv, 1u);     // publish
        }
    }
}

// ---------------- kernel 1: fc1 + BatchNorm (batch stats) -> seq[:,0,:] ----------------
__global__ void __launch_bounds__(256) fc1_bn_kernel(
    const float* __restrict__ x,     // [16,512]
    const float* __restrict__ w,     // [256,512]
    const float* __restrict__ bias,  // [256]
    const float* __restrict__ gam,   // [256]
    const float* __restrict__ bet)   // [256]
{
    __shared__ float xs[NB*ENC];     // 32 KB
    int tid = threadIdx.x;
    for (int i = tid; i < NB*ENC/4; i += 256)
        ((float4*)xs)[i] = ((const float4*)x)[i];
    __syncthreads();

    int j = tid;
    float f[NB];
    #pragma unroll
    for (int b = 0; b < NB; b++) f[b] = bias[j];

    const float4* w4 = (const float4*)(w + j*ENC);
    for (int k4 = 0; k4 < ENC/4; k4++) {
        float4 ww = w4[k4];
        #pragma unroll
        for (int b = 0; b < NB; b++) {
            float4 xx = ((float4*)xs)[b*(ENC/4) + k4];
            f[b] += ww.x*xx.x + ww.y*xx.y + ww.z*xx.z + ww.w*xx.w;
        }
    }
    float mu = 0.f;
    #pragma unroll
    for (int b = 0; b < NB; b++) mu += f[b];
    mu *= (1.0f/NB);
    float var = 0.f;
    #pragma unroll
    for (int b = 0; b < NB; b++) { float d = f[b]-mu; var += d*d; }
    var *= (1.0f/NB);
    float s = rsqrtf(var + 1e-5f) * gam[j];
    float bb = bet[j];
    #pragma unroll
    for (int b = 0; b < NB; b++)
        g_seq[b*(LSEQ*EMB) + j] = (f[b]-mu)*s + bb;   // t = 0
}

// ---------------- kernel 2: embedding gather -> seq[:,1:,:] ----------------
__global__ void embed_kernel(const int* __restrict__ y,      // [16,255]
                             const float* __restrict__ emb)  // [32000,256]
{
    int blk = blockIdx.x;
    int b = blk / (LSEQ-1), t = blk % (LSEQ-1);
    int row = y[b*(LSEQ-1) + t];
    const float4* src = (const float4*)(emb + (long)row*EMB);
    float4* dst = (float4*)(g_seq + b*(LSEQ*EMB) + (t+1)*EMB);
    dst[threadIdx.x] = src[threadIdx.x];
}

// ---------------- tf32/bf16 helpers ----------------
__device__ __forceinline__ unsigned f2tf32(float v)
{
    unsigned u;
    asm("cvt.rna.tf32.f32 %0, %1;" : "=r"(u) : "f"(v));
    return u;
}

__device__ __forceinline__ void mma_tf32(float* c, const unsigned* a, const unsigned* b)
{
    asm volatile(
        "mma.sync.aligned.m16n8k8.row.col.f32.tf32.tf32.f32 "
        "{%0,%1,%2,%3}, {%4,%5,%6,%7}, {%8,%9}, {%0,%1,%2,%3};\n"
        : "+f"(c[0]), "+f"(c[1]), "+f"(c[2]), "+f"(c[3])
        : "r"(a[0]), "r"(a[1]), "r"(a[2]), "r"(a[3]), "r"(b[0]), "r"(b[1]));
}

__device__ __forceinline__ void mma_bf16(float* c, const unsigned* a, const unsigned* b)
{
    asm volatile(
        "mma.sync.aligned.m16n8k16.row.col.f32.bf16.bf16.f32 "
        "{%0,%1,%2,%3}, {%4,%5,%6,%7}, {%8,%9}, {%0,%1,%2,%3};\n"
        : "+f"(c[0]), "+f"(c[1]), "+f"(c[2]), "+f"(c[3])
        : "r"(a[0]), "r"(a[1]), "r"(a[2]), "r"(a[3]), "r"(b[0]), "r"(b[1]));
}

#define TF_KS    32
#define TF_AST   36
#define TF_TILE  (128*TF_AST)
#define TF_SMEM  (2*2*TF_TILE*4)

// ---------------- kernel 3: generic tf32 GEMM  C = A[M,K] * B[N,K]^T (+bias) ----------------
template<int MODE, bool DOTANH>
__global__ void __launch_bounds__(256, 2) gemm_tf32(
    const float* __restrict__ A, const float* __restrict__ B,
    const float* __restrict__ bias0, const float* __restrict__ bias1,
    float* __restrict__ C, int N, int K, int Cld)
{
    extern __shared__ float smf[];
    const int tid  = threadIdx.x;
    const int lane = tid & 31;
    const int warp = tid >> 5;
    const int warp_m = warp >> 1;
    const int warp_n = warp & 1;
    const int m0 = blockIdx.y * 128;
    const int n0 = blockIdx.x * 128;
    const int g = lane >> 2;
    const int t = lane & 3;

    unsigned sbase = (unsigned)__cvta_generic_to_shared(smf);

    auto issue_load = [&](int buf, int k0) {
        #pragma unroll
        for (int rep = 0; rep < 8; rep++) {
            int i   = tid + rep*256;
            int mat = i >> 10;
            int idx = i & 1023;
            int row = idx >> 3;
            int q   = idx & 7;
            unsigned daddr = sbase + ((buf*2 + mat)*TF_TILE + row*TF_AST + q*4)*4;
            const float* gsrc = (mat ? B + (long)(n0+row)*K
                                     : A + (long)(m0+row)*K) + k0 + q*4;
            asm volatile("cp.async.cg.shared.global [%0], [%1], 16;\n"
                         :: "r"(daddr), "l"(gsrc));
        }
        asm volatile("cp.async.commit_group;\n");
    };

    float acc[2][8][4];
    #pragma unroll
    for (int i = 0; i < 2; i++)
        #pragma unroll
        for (int j = 0; j < 8; j++)
            #pragma unroll
            for (int r = 0; r < 4; r++) acc[i][j][r] = 0.f;

    issue_load(0, 0);

    int nst = K / TF_KS;
    int buf = 0;
    for (int ks = 0; ks < nst; ks++) {
        asm volatile("cp.async.wait_group 0;\n");
        __syncthreads();
        if (ks + 1 < nst) issue_load(buf ^ 1, (ks+1)*TF_KS);

        const float* sA = smf + (buf*2 + 0)*TF_TILE;
        const float* sB = smf + (buf*2 + 1)*TF_TILE;

        #pragma unroll
        for (int k8 = 0; k8 < 4; k8++) {
            int kc = k8*8 + t;
            unsigned af[2][4];
            #pragma unroll
            for (int im = 0; im < 2; im++) {
                int rb = warp_m*32 + im*16 + g;
                af[im][0] = f2tf32(sA[rb*TF_AST + kc]);
                af[im][1] = f2tf32(sA[(rb+8)*TF_AST + kc]);
                af[im][2] = f2tf32(sA[rb*TF_AST + kc + 4]);
                af[im][3] = f2tf32(sA[(rb+8)*TF_AST + kc + 4]);
            }
            unsigned bf[8][2];
            #pragma unroll
            for (int in = 0; in < 8; in++) {
                int nc = warp_n*64 + in*8 + g;
                bf[in][0] = f2tf32(sB[nc*TF_AST + kc]);
                bf[in][1] = f2tf32(sB[nc*TF_AST + kc + 4]);
            }
            #pragma unroll
            for (int im = 0; im < 2; im++)
                #pragma unroll
                for (int in = 0; in < 8; in++)
                    mma_tf32(acc[im][in], af[im], bf[in]);
        }
        buf ^= 1;
        __syncthreads();
    }

    #pragma unroll
    for (int im = 0; im < 2; im++) {
        int row = m0 + warp_m*32 + im*16 + g;
        #pragma unroll
        for (int in = 0; in < 8; in++) {
            int col = n0 + warp_n*64 + in*8 + t*2;
            float bs0 = 0.f, bs1 = 0.f;
            if (bias0) { bs0 += bias0[col]; bs1 += bias0[col+1]; }
            if (bias1) { bs0 += bias1[col]; bs1 += bias1[col+1]; }
            float v00 = acc[im][in][0] + bs0, v01 = acc[im][in][1] + bs1;
            float v10 = acc[im][in][2] + bs0, v11 = acc[im][in][3] + bs1;
            if (DOTANH) { v00 = tanhf(v00); v01 = tanhf(v01);
                          v10 = tanhf(v10); v11 = tanhf(v11); }
            if (MODE == 0) {
                *(float2*)(C + (long)row*Cld + col)     = make_float2(v00, v01);
                *(float2*)(C + (long)(row+8)*Cld + col) = make_float2(v10, v11);
            } else {
                int b0 = row >> 8, t0 = row & 255;
                int b1 = (row+8) >> 8, t1 = (row+8) & 255;
                C[(long)t0*(N*NB) + col*NB + b0]     = v00;
                C[(long)t0*(N*NB) + (col+1)*NB + b0] = v01;
                C[(long)t1*(N*NB) + col*NB + b1]     = v10;
                C[(long)t1*(N*NB) + (col+1)*NB + b1] = v11;
            }
        }
    }
}

// ---------------- kernel 4: persistent LSTM (128 CTAs, direct-fragment exchange) ----------------
// h ring stored as packed bf16 hi/lo u32 planes in MMA-fragment layout (producer-side split).
// Consumers __ldcg fragments straight from L2. Release/acquire barrier, named bar for tail.
#define LSTM_CTAS 128

__global__ void __launch_bounds__(256, 1) lstm_kernel(
    const float* __restrict__ xw,
    const float* __restrict__ Whh,   // [2048,512]
    float* __restrict__ out, long bstr, long tstr)
{
    __shared__ float red[8*272];     // warp partials, row stride 17
    __shared__ float gxw[256];       // xw stash for producers

    int tid = threadIdx.x, cta = blockIdx.x;
    int gate = tid >> 6, dl = (tid >> 4) & 3, b = tid & 15;
    int j  = gate*512 + cta*4 + dl;

    const int w    = tid >> 5;
    const int lane = tid & 31;
    const int g    = lane >> 2;
    const int tq   = lane & 3;

    // --- preload W fragments (hi/lo bf16 packed pairs) for this warp's k-slice ---
    unsigned wh[2][4][2], wl[2][4][2];
    #pragma unroll
    for (int nb = 0; nb < 2; nb++) {
        int jl = nb*8 + g;
        const float* wrow = Whh + (long)((jl>>2)*512 + cta*4 + (jl&3))*512 + w*64;
        #pragma unroll
        for (int c = 0; c < 4; c++) {
            float2 p0 = *(const float2*)(wrow + c*16 + 2*tq);
            float2 p1 = *(const float2*)(wrow + c*16 + 2*tq + 8);
            __nv_bfloat162 h0 = __floats2bfloat162_rn(p0.x, p0.y);
            __nv_bfloat162 h1 = __floats2bfloat162_rn(p1.x, p1.y);
            wh[nb][c][0] = *(unsigned*)&h0;
            wh[nb][c][1] = *(unsigned*)&h1;
            __nv_bfloat162 l0 = __floats2bfloat162_rn(
                p0.x - __bfloat162float(h0.x), p0.y - __bfloat162float(h0.y));
            __nv_bfloat162 l1 = __floats2bfloat162_rn(
                p1.x - __bfloat162float(h1.x), p1.y - __bfloat162float(h1.y));
            wl[nb][c][0] = *(unsigned*)&l0;
            wl[nb][c][1] = *(unsigned*)&l1;
        }
    }

    // read gen base BEFORE any arrival (race-free: publish needs all CTAs arrived)
    unsigned gen0 = ld_acq(&g_genv);

    // zero slot-0 planes (hi+lo = 8192 u32)
    for (int i = cta*256 + tid; i < 2*16*256; i += LSTM_CTAS*256)
        g_hP[i] = 0u;

    const int bb  = tid & 15;        // producer mapping (tid<64)
    const int ddl = tid >> 4;
    float c_reg = 0.f;

    __syncthreads();
    if (tid == 0) bar_arrive(cta);   // initial barrier -> gen0+1

    for (int t = 0; t < LSEQ; t++) {
        unsigned tgt = gen0 + 1 + (unsigned)t;
        while (ld_acq(&g_genv) < tgt) { }

        // xw load + stash
        gxw[tid] = xw[(long)t*(G4*NB) + j*NB + b];

        // fragments straight from L2 (packed bf16 hi/lo planes)
        const unsigned* hiB = g_hP + (t & 1)*8192;
        const unsigned* loB = hiB + 4096;

        float acc[2][2][4];
        #pragma unroll
        for (int nb = 0; nb < 2; nb++)
            #pragma unroll
            for (int p = 0; p < 2; p++)
                #pragma unroll
                for (int r = 0; r < 4; r++) acc[nb][p][r] = 0.f;

        #pragma unroll
        for (int c = 0; c < 4; c++) {
            int kb2 = w*32 + c*8;
            unsigned ah[4], al[4];
            ah[0] = __ldcg(hiB + g*256 + kb2 + tq);
            ah[1] = __ldcg(hiB + (g+8)*256 + kb2 + tq);
            ah[2] = __ldcg(hiB + g*256 + kb2 + tq + 4);
            ah[3] = __ldcg(hiB + (g+8)*256 + kb2 + tq + 4);
            al[0] = __ldcg(loB + g*256 + kb2 + tq);
            al[1] = __ldcg(loB + (g+8)*256 + kb2 + tq);
            al[2] = __ldcg(loB + g*256 + kb2 + tq + 4);
            al[3] = __ldcg(loB + (g+8)*256 + kb2 + tq + 4);
            int p = c & 1;
            #pragma unroll
            for (int nb = 0; nb < 2; nb++) {
                mma_bf16(acc[nb][p], ah, wh[nb][c]);
                mma_bf16(acc[nb][p], ah, wl[nb][c]);
                mma_bf16(acc[nb][p], al, wh[nb][c]);
            }
        }

        // warp partials -> red (rows g/g+8 = b, cols nb*8+2tq(+1) = jl)
        #pragma unroll
        for (int nb = 0; nb < 2; nb++) {
            int cbase = nb*8 + 2*tq;
            red[w*272 + g*17 + cbase]         = acc[nb][0][0] + acc[nb][1][0];
            red[w*272 + g*17 + cbase + 1]     = acc[nb][0][1] + acc[nb][1][1];
            red[w*272 + (g+8)*17 + cbase]     = acc[nb][0][2] + acc[nb][1][2];
            red[w*272 + (g+8)*17 + cbase + 1] = acc[nb][0][3] + acc[nb][1][3];
        }
        __syncthreads();

        if (tid < 64) {
            // gate sums: xw + 8 warp partials, all 4 gates for (bb, d=cta*4+ddl)
            float sv[4];
            #pragma unroll
            for (int gg = 0; gg < 4; gg++) {
                float s = gxw[gg*64 + ddl*16 + bb];
                #pragma unroll
                for (int ww = 0; ww < 8; ww++)
                    s += red[ww*272 + bb*17 + gg*4 + ddl];
                sv[gg] = s;
            }
            float ig = sigf(sv[0]);
            float fg = sigf(sv[1]);
            float gv = tanhf(sv[2]);
            float og = sigf(sv[3]);
            c_reg = fg*c_reg + ig*gv;
            float h = og * tanhf(c_reg);

            // pack bf16 hi/lo pair with partner (ddl^1 via shfl_xor 16, same warp)
            float hq = __shfl_xor_sync(0xffffffffu, h, 16);
            if ((ddl & 1) == 0) {
                __nv_bfloat162 hv = __floats2bfloat162_rn(h, hq);
                __nv_bfloat162 lv = __floats2bfloat162_rn(
                    h - __bfloat162float(hv.x), hq - __bfloat162float(hv.y));
                unsigned* dst = g_hP + ((t+1) & 1)*8192 + bb*256 + cta*2 + (ddl >> 1);
                st_cg_u32(dst,        *(unsigned*)&hv);
                st_cg_u32(dst + 4096, *(unsigned*)&lv);
            }
            out[bb*bstr + (long)t*tstr + cta*4 + ddl] = h;

            asm volatile("bar.sync 1, 64;" ::: "memory");
            if (tid == 0) bar_arrive(cta);
        }
    }
}

// ---------------- kernel 5: causal self-attention (CTA per (q,b)) ----------------
__global__ void __launch_bounds__(256) attn_kernel()
{
    __shared__ float hqs[512];
    __shared__ float sc[256];
    __shared__ float red[256];
    __shared__ float4 red4[256];
    int q = blockIdx.x, b = blockIdx.y;
    int tid = threadIdx.x;
    int nk = q + 1;
    float* catb = g_cat + (long)b*(LSEQ*2*DEC);

    if (tid < 128)
        ((float4*)hqs)[tid] = ((const float4*)(catb + q*1024 + 512))[tid];
    __syncthreads();

    int w = tid >> 5, lane = tid & 31;
    for (int k = w; k < nk; k += 8) {
        const float4* hk = (const float4*)(catb + k*1024 + 512);
        float s = 0.f;
        #pragma unroll
        for (int i = 0; i < 4; i++) {
            float4 a = ((float4*)hqs)[lane + 32*i];
            float4 c = hk[lane + 32*i];
            s += a.x*c.x + a.y*c.y + a.z*c.z + a.w*c.w;
        }
        #pragma unroll
        for (int off = 16; off; off >>= 1) s += __shfl_xor_sync(0xffffffffu, s, off);
        if (lane == 0) sc[k] = s;
    }
    __syncthreads();

    float v = (tid < nk) ? sc[tid] : -INFINITY;
    red[tid] = v; __syncthreads();
    #pragma unroll
    for (int s = 128; s; s >>= 1) {
        if (tid < s) red[tid] = fmaxf(red[tid], red[tid+s]);
        __syncthreads();
    }
    float mx = red[0]; __syncthreads();
    float e = (tid < nk) ? __expf(v - mx) : 0.f;
    red[tid] = e; __syncthreads();
    #pragma unroll
    for (int s = 128; s; s >>= 1) {
        if (tid < s) red[tid] += red[tid+s];
        __syncthreads();
    }
    float inv = 1.f / red[0];
    __syncthreads();
    if (tid < nk) sc[tid] = e * inv;
    __syncthreads();

    // mix: float4 per thread, 2 k-stripes
    int dq = tid & 127;
    int stripe = tid >> 7;
    float4 a = make_float4(0.f, 0.f, 0.f, 0.f);
    for (int k = stripe; k < nk; k += 2) {
        float wk = sc[k];
        float4 hv = *(const float4*)(catb + k*1024 + 512 + dq*4);
        a.x += wk*hv.x; a.y += wk*hv.y; a.z += wk*hv.z; a.w += wk*hv.w;
    }
    red4[tid] = a;
    __syncthreads();
    if (tid < 128) {
        float4 b0 = red4[tid], b1 = red4[tid+128];
        float4 r = make_float4(b0.x+b1.x, b0.y+b1.y, b0.z+b1.z, b0.w+b1.w);
        *(float4*)(catb + q*1024 + dq*4) = r;
    }
}

// ---------------- kernel 6: fc2 single-pass tf32 tensor GEMM (proven) ----------------
__global__ void __launch_bounds__(256, 2) fc2_tf32_kernel(
    const float* __restrict__ A, const float* __restrict__ B,
    const float* __restrict__ bias, float* __restrict__ C)
{
    extern __shared__ float smf[];
    const int tid  = threadIdx.x;
    const int lane = tid & 31;
    const int warp = tid >> 5;
    const int warp_m = warp >> 1;
    const int warp_n = warp & 1;
    const int m0 = blockIdx.y * 128;
    const int n0 = blockIdx.x * 128;
    const int g = lane >> 2;
    const int t = lane & 3;

    unsigned sbase = (unsigned)__cvta_generic_to_shared(smf);

    auto issue_load = [&](int buf, int k0) {
        #pragma unroll
        for (int rep = 0; rep < 8; rep++) {
            int i   = tid + rep*256;
            int mat = i >> 10;
            int idx = i & 1023;
            int row = idx >> 3;
            int q   = idx & 7;
            unsigned daddr = sbase + ((buf*2 + mat)*TF_TILE + row*TF_AST + q*4)*4;
            const float* gsrc = (mat ? B + (long)(n0+row)*DEC
                                     : A + (long)(m0+row)*DEC) + k0 + q*4;
            asm volatile("cp.async.cg.shared.global [%0], [%1], 16;\n"
                         :: "r"(daddr), "l"(gsrc));
        }
        asm volatile("cp.async.commit_group;\n");
    };

    float acc[2][8][4];
    #pragma unroll
    for (int i = 0; i < 2; i++)
        #pragma unroll
        for (int j = 0; j < 8; j++)
            #pragma unroll
            for (int r = 0; r < 4; r++) acc[i][j][r] = 0.f;

    issue_load(0, 0);

    int buf = 0;
    for (int ks = 0; ks < DEC/TF_KS; ks++) {
        asm volatile("cp.async.wait_group 0;\n");
        __syncthreads();
        if (ks + 1 < DEC/TF_KS) issue_load(buf ^ 1, (ks+1)*TF_KS);

        const float* sA = smf + (buf*2 + 0)*TF_TILE;
        const float* sB = smf + (buf*2 + 1)*TF_TILE;

        #pragma unroll
        for (int k8 = 0; k8 < 4; k8++) {
            int kc = k8*8 + t;
            unsigned af[2][4];
            #pragma unroll
            for (int im = 0; im < 2; im++) {
                int rb = warp_m*32 + im*16 + g;
                af[im][0] = f2tf32(sA[rb*TF_AST + kc]);
                af[im][1] = f2tf32(sA[(rb+8)*TF_AST + kc]);
                af[im][2] = f2tf32(sA[rb*TF_AST + kc + 4]);
                af[im][3] = f2tf32(sA[(rb+8)*TF_AST + kc + 4]);
            }
            unsigned bf[8][2];
            #pragma unroll
            for (int in = 0; in < 8; in++) {
                int nc = warp_n*64 + in*8 + g;
                bf[in][0] = f2tf32(sB[nc*TF_AST + kc]);
                bf[in][1] = f2tf32(sB[nc*TF_AST + kc + 4]);
            }
            #pragma unroll
            for (int im = 0; im < 2; im++)
                #pragma unroll
                for (int in = 0; in < 8; in++)
                    mma_tf32(acc[im][in], af[im], bf[in]);
        }
        buf ^= 1;
        __syncthreads();
    }

    #pragma unroll
    for (int im = 0; im < 2; im++) {
        int row = m0 + warp_m*32 + im*16 + g;
        #pragma unroll
        for (int in = 0; in < 8; in++) {
            int col = n0 + warp_n*64 + in*8 + t*2;
            float b0 = bias[col], b1 = bias[col+1];
            float2 v0 = make_float2(acc[im][in][0] + b0, acc[im][in][1] + b1);
            float2 v1 = make_float2(acc[im][in][2] + b0, acc[im][in][3] + b1);
            *(float2*)(C + (long)row*NV + col)     = v0;
            *(float2*)(C + (long)(row+8)*NV + col) = v1;
        }
    }
}

// ---------------- launch ----------------
extern "C" void kernel_launch(void* const* d_in, const int* in_sizes, int n_in,
                              void* d_out, int out_size)
{
    const float* x       = (const float*)d_in[0];
    const int*   y       = (const int*)  d_in[1];
    const float* fc1_w   = (const float*)d_in[2];
    const float* fc1_b   = (const float*)d_in[3];
    const float* bn_g    = (const float*)d_in[4];
    const float* bn_b    = (const float*)d_in[5];
    const float* emb     = (const float*)d_in[6];
    const float* l1_Wih  = (const float*)d_in[7];
    const float* l1_Whh  = (const float*)d_in[8];
    const float* l1_bih  = (const float*)d_in[9];
    const float* l1_bhh  = (const float*)d_in[10];
    const float* attn_W  = (const float*)d_in[11];
    const float* dc_Wih  = (const float*)d_in[12];
    const float* dc_Whh  = (const float*)d_in[13];
    const float* dc_bih  = (const float*)d_in[14];
    const float* dc_bhh  = (const float*)d_in[15];
    const float* fc2_w   = (const float*)d_in[16];
    const float* fc2_b   = (const float*)d_in[17];
    float* out = (float*)d_out;

    float *p_seq, *p_xw, *p_cat, *p_attn, *p_h2;
    cudaGetSymbolAddress((void**)&p_seq,  g_seq);
    cudaGetSymbolAddress((void**)&p_xw,   g_xw);
    cudaGetSymbolAddress((void**)&p_cat,  g_cat);
    cudaGetSymbolAddress((void**)&p_attn, g_attn);
    cudaGetSymbolAddress((void**)&p_h2,   g_h2);

    cudaFuncSetAttribute(fc2_tf32_kernel, cudaFuncAttributeMaxDynamicSharedMemorySize, TF_SMEM);
    cudaFuncSetAttribute(gemm_tf32<1,false>, cudaFuncAttributeMaxDynamicSharedMemorySize, TF_SMEM);
    cudaFuncSetAttribute(gemm_tf32<0,true>,  cudaFuncAttributeMaxDynamicSharedMemorySize, TF_SMEM);

    // 1. fc1 + BN
    fc1_bn_kernel<<<1, 256>>>(x, fc1_w, fc1_b, bn_g, bn_b);
    // 2. embedding
    embed_kernel<<<NB*(LSEQ-1), 64>>>(y, emb);
    // 3. xw1 = seq @ l1_Wih^T + biases   (tf32, LSTM layout)
    gemm_tf32<1,false><<<dim3(G4/128, MROWS/128), 256, TF_SMEM>>>(
        p_seq, l1_Wih, l1_bih, l1_bhh, p_xw, G4, EMB, 0);
    // 4. LSTM 1  ->  g_cat[b][t][512:1024]
    lstm_kernel<<<LSTM_CTAS, 256>>>(
        p_xw, l1_Whh, p_cat + 512, (long)LSEQ*2*DEC, (long)2*DEC);
    // 5. attention -> g_cat[b][t][0:512]
    attn_kernel<<<dim3(LSEQ, NB), 256>>>();
    // 6. attn = tanh(cat @ attn_W^T)   (tf32)
    gemm_tf32<0,true><<<dim3(DEC/128, MROWS/128), 256, TF_SMEM>>>(
        p_cat, attn_W, nullptr, nullptr, p_attn, DEC, 2*DEC, DEC);
    // 7. xw2 = attn @ dc_Wih^T + biases (tf32, LSTM layout)
    gemm_tf32<1,false><<<dim3(G4/128, MROWS/128), 256, TF_SMEM>>>(
        p_attn, dc_Wih, dc_bih, dc_bhh, p_xw, G4, DEC, 0);
    // 8. LSTM 2 -> g_h2[m][d]
    lstm_kernel<<<LSTM_CTAS, 256>>>(
        p_xw, dc_Whh, p_h2, (long)LSEQ*DEC, (long)DEC);
    // 9. fc2 single-pass tf32 tensor GEMM -> d_out
    fc2_tf32_kernel<<<dim3(NV/128, MROWS/128), 256, TF_SMEM>>>(
        p_h2, fc2_w, fc2_b, out);
}

// round 16
// speedup vs baseline: 1.0905x; 1.0905x over previous
#include <cuda_runtime.h>
#include <cuda_bf16.h>
#include <math.h>

// ---------------- problem constants ----------------
#define NB   16          // batch
#define LSEQ 256         // sequence length (TY+1)
#define ENC  512
#define EMB  256
#define DEC  512
#define NV   32000
#define G4   2048        // 4*DEC
#define MROWS 4096       // NB*LSEQ

// ---------------- scratch (__device__ globals; no allocs) ----------------
__device__ float g_seq [NB*LSEQ*EMB];        //  4 MB  [b][t][EMB]
__device__ float g_xw  [LSEQ*G4*NB];         // 32 MB  [t][j][b]
__device__ float g_cat [NB*LSEQ*2*DEC];      // 16 MB  [b][t][ mix(512) | h1(512) ]
__device__ float g_attn[MROWS*DEC];          //  8 MB  [m][512]
__device__ float g_h2  [MROWS*DEC];          //  8 MB  [m][512]
// h double buffer, TRANSPOSED layout: word = q*2048 + d*4 + br  (b = 4q+br)
__device__ float g_hT  [2*NB*DEC];
// flag-array barrier: one monotonic counter per CTA, 32B apart
#define FLAG_STRIDE 8
__device__ unsigned g_flag[128*FLAG_STRIDE];

__device__ __forceinline__ float sigf(float x){ return 1.0f/(1.0f+__expf(-x)); }

__device__ __forceinline__ unsigned ld_acq(const unsigned* p){
    unsigned v;
    asm volatile("ld.acquire.gpu.global.u32 %0, [%1];" : "=r"(v) : "l"(p) : "memory");
    return v;
}
__device__ __forceinline__ void st_rel(unsigned* p, unsigned v){
    asm volatile("st.release.gpu.global.u32 [%0], %1;" :: "l"(p), "r"(v) : "memory");
}

// ---------------- kernel 1: fc1 + BatchNorm (batch stats) -> seq[:,0,:] ----------------
__global__ void __launch_bounds__(256) fc1_bn_kernel(
    const float* __restrict__ x,     // [16,512]
    const float* __restrict__ w,     // [256,512]
    const float* __restrict__ bias,  // [256]
    const float* __restrict__ gam,   // [256]
    const float* __restrict__ bet)   // [256]
{
    __shared__ float xs[NB*ENC];     // 32 KB
    int tid = threadIdx.x;
    for (int i = tid; i < NB*ENC/4; i += 256)
        ((float4*)xs)[i] = ((const float4*)x)[i];
    __syncthreads();

    int j = tid;
    float f[NB];
    #pragma unroll
    for (int b = 0; b < NB; b++) f[b] = bias[j];

    const float4* w4 = (const float4*)(w + j*ENC);
    for (int k4 = 0; k4 < ENC/4; k4++) {
        float4 ww = w4[k4];
        #pragma unroll
        for (int b = 0; b < NB; b++) {
            float4 xx = ((float4*)xs)[b*(ENC/4) + k4];
            f[b] += ww.x*xx.x + ww.y*xx.y + ww.z*xx.z + ww.w*xx.w;
        }
    }
    float mu = 0.f;
    #pragma unroll
    for (int b = 0; b < NB; b++) mu += f[b];
    mu *= (1.0f/NB);
    float var = 0.f;
    #pragma unroll
    for (int b = 0; b < NB; b++) { float d = f[b]-mu; var += d*d; }
    var *= (1.0f/NB);
    float s = rsqrtf(var + 1e-5f) * gam[j];
    float bb = bet[j];
    #pragma unroll
    for (int b = 0; b < NB; b++)
        g_seq[b*(LSEQ*EMB) + j] = (f[b]-mu)*s + bb;   // t = 0
}

// ---------------- kernel 2: embedding gather -> seq[:,1:,:] ----------------
__global__ void embed_kernel(const int* __restrict__ y,      // [16,255]
                             const float* __restrict__ emb)  // [32000,256]
{
    int blk = blockIdx.x;
    int b = blk / (LSEQ-1), t = blk % (LSEQ-1);
    int row = y[b*(LSEQ-1) + t];
    const float4* src = (const float4*)(emb + (long)row*EMB);
    float4* dst = (float4*)(g_seq + b*(LSEQ*EMB) + (t+1)*EMB);
    dst[threadIdx.x] = src[threadIdx.x];
}

// ---------------- tf32/bf16 helpers ----------------
__device__ __forceinline__ unsigned f2tf32(float v)
{
    unsigned u;
    asm("cvt.rna.tf32.f32 %0, %1;" : "=r"(u) : "f"(v));
    return u;
}

__device__ __forceinline__ void mma_tf32(float* c, const unsigned* a, const unsigned* b)
{
    asm volatile(
        "mma.sync.aligned.m16n8k8.row.col.f32.tf32.tf32.f32 "
        "{%0,%1,%2,%3}, {%4,%5,%6,%7}, {%8,%9}, {%0,%1,%2,%3};\n"
        : "+f"(c[0]), "+f"(c[1]), "+f"(c[2]), "+f"(c[3])
        : "r"(a[0]), "r"(a[1]), "r"(a[2]), "r"(a[3]), "r"(b[0]), "r"(b[1]));
}

__device__ __forceinline__ void mma_bf16(float* c, const unsigned* a, const unsigned* b)
{
    asm volatile(
        "mma.sync.aligned.m16n8k16.row.col.f32.bf16.bf16.f32 "
        "{%0,%1,%2,%3}, {%4,%5,%6,%7}, {%8,%9}, {%0,%1,%2,%3};\n"
        : "+f"(c[0]), "+f"(c[1]), "+f"(c[2]), "+f"(c[3])
        : "r"(a[0]), "r"(a[1]), "r"(a[2]), "r"(a[3]), "r"(b[0]), "r"(b[1]));
}

#define TF_KS    32
#define TF_AST   36                        // smem row stride in floats (conflict-free)
#define TF_TILE  (128*TF_AST)              // floats per matrix tile
#define TF_SMEM  (2*2*TF_TILE*4)           // 73728 B

// ---------------- kernel 3: generic tf32 GEMM  C = A[M,K] * B[N,K]^T (+bias) ----------------
// MODE 0: C[m*Cld+n] (+tanh opt);  MODE 1: C[t*(N*16) + n*16 + b], m = b*256+t
template<int MODE, bool DOTANH>
__global__ void __launch_bounds__(256, 2) gemm_tf32(
    const float* __restrict__ A, const float* __restrict__ B,
    const float* __restrict__ bias0, const float* __restrict__ bias1,
    float* __restrict__ C, int N, int K, int Cld)
{
    extern __shared__ float smf[];
    const int tid  = threadIdx.x;
    const int lane = tid & 31;
    const int warp = tid >> 5;
    const int warp_m = warp >> 1;
    const int warp_n = warp & 1;
    const int m0 = blockIdx.y * 128;
    const int n0 = blockIdx.x * 128;
    const int g = lane >> 2;
    const int t = lane & 3;

    unsigned sbase = (unsigned)__cvta_generic_to_shared(smf);

    auto issue_load = [&](int buf, int k0) {
        #pragma unroll
        for (int rep = 0; rep < 8; rep++) {
            int i   = tid + rep*256;
            int mat = i >> 10;
            int idx = i & 1023;
            int row = idx >> 3;
            int q   = idx & 7;
            unsigned daddr = sbase + ((buf*2 + mat)*TF_TILE + row*TF_AST + q*4)*4;
            const float* gsrc = (mat ? B + (long)(n0+row)*K
                                     : A + (long)(m0+row)*K) + k0 + q*4;
            asm volatile("cp.async.cg.shared.global [%0], [%1], 16;\n"
                         :: "r"(daddr), "l"(gsrc));
        }
        asm volatile("cp.async.commit_group;\n");
    };

    float acc[2][8][4];
    #pragma unroll
    for (int i = 0; i < 2; i++)
        #pragma unroll
        for (int j = 0; j < 8; j++)
            #pragma unroll
            for (int r = 0; r < 4; r++) acc[i][j][r] = 0.f;

    issue_load(0, 0);

    int nst = K / TF_KS;
    int buf = 0;
    for (int ks = 0; ks < nst; ks++) {
        asm volatile("cp.async.wait_group 0;\n");
        __syncthreads();
        if (ks + 1 < nst) issue_load(buf ^ 1, (ks+1)*TF_KS);

        const float* sA = smf + (buf*2 + 0)*TF_TILE;
        const float* sB = smf + (buf*2 + 1)*TF_TILE;

        #pragma unroll
        for (int k8 = 0; k8 < 4; k8++) {
            int kc = k8*8 + t;
            unsigned af[2][4];
            #pragma unroll
            for (int im = 0; im < 2; im++) {
                int rb = warp_m*32 + im*16 + g;
                af[im][0] = f2tf32(sA[rb*TF_AST + kc]);
                af[im][1] = f2tf32(sA[(rb+8)*TF_AST + kc]);
                af[im][2] = f2tf32(sA[rb*TF_AST + kc + 4]);
                af[im][3] = f2tf32(sA[(rb+8)*TF_AST + kc + 4]);
            }
            unsigned bf[8][2];
            #pragma unroll
            for (int in = 0; in < 8; in++) {
                int nc = warp_n*64 + in*8 + g;
                bf[in][0] = f2tf32(sB[nc*TF_AST + kc]);
                bf[in][1] = f2tf32(sB[nc*TF_AST + kc + 4]);
            }
            #pragma unroll
            for (int im = 0; im < 2; im++)
                #pragma unroll
                for (int in = 0; in < 8; in++)
                    mma_tf32(acc[im][in], af[im], bf[in]);
        }
        buf ^= 1;
        __syncthreads();
    }

    #pragma unroll
    for (int im = 0; im < 2; im++) {
        int row = m0 + warp_m*32 + im*16 + g;
        #pragma unroll
        for (int in = 0; in < 8; in++) {
            int col = n0 + warp_n*64 + in*8 + t*2;
            float bs0 = 0.f, bs1 = 0.f;
            if (bias0) { bs0 += bias0[col]; bs1 += bias0[col+1]; }
            if (bias1) { bs0 += bias1[col]; bs1 += bias1[col+1]; }
            float v00 = acc[im][in][0] + bs0, v01 = acc[im][in][1] + bs1;
            float v10 = acc[im][in][2] + bs0, v11 = acc[im][in][3] + bs1;
            if (DOTANH) { v00 = tanhf(v00); v01 = tanhf(v01);
                          v10 = tanhf(v10); v11 = tanhf(v11); }
            if (MODE == 0) {
                *(float2*)(C + (long)row*Cld + col)     = make_float2(v00, v01);
                *(float2*)(C + (long)(row+8)*Cld + col) = make_float2(v10, v11);
            } else {
                int b0 = row >> 8, t0 = row & 255;
                int b1 = (row+8) >> 8, t1 = (row+8) & 255;
                C[(long)t0*(N*NB) + col*NB + b0]     = v00;
                C[(long)t0*(N*NB) + (col+1)*NB + b0] = v01;
                C[(long)t1*(N*NB) + col*NB + b1]     = v10;
                C[(long)t1*(N*NB) + (col+1)*NB + b1] = v11;
            }
        }
    }
}

// ---------------- kernel 4: persistent LSTM (128 CTAs, bf16 hi/lo tensor cores) ----------------
// R12 structure; only the grid barrier is replaced by a flag-array
// (contention-free release-store arrivals + warp-0 acquire polling).
#define LSTM_CTAS 128
#define HP2  260                       // plane row stride (u32): bank = 4g+tq, bijective
#define SM_HI   0                      // 16*260 u32
#define SM_LO   4160                   // 16*260 u32
#define SM_GX   8320                   // 256 floats
#define SM_RED  8576                   // 8*272 floats
#define LSTM_SMEM ((8576 + 2176)*4)    // 43008 B

__global__ void __launch_bounds__(256, 1) lstm_kernel(
    const float* __restrict__ xw,
    const float* __restrict__ Whh,   // [2048,512]
    float* __restrict__ out, long bstr, long tstr)
{
    extern __shared__ unsigned smu[];
    unsigned* hiP = smu + SM_HI;
    unsigned* loP = smu + SM_LO;
    float*    gx  = (float*)(smu + SM_GX);
    float*    red = (float*)(smu + SM_RED);

    int tid = threadIdx.x, cta = blockIdx.x;
    int gate = tid >> 6, dl = (tid >> 4) & 3, b = tid & 15;
    int j  = gate*512 + cta*4 + dl;

    const int w    = tid >> 5;       // warp = k-slice owner
    const int lane = tid & 31;
    const int g    = lane >> 2;      // 0..7
    const int tq   = lane & 3;       // 0..3

    // --- preload W fragments (hi/lo bf16 packed pairs) for this warp's k-slice ---
    unsigned wh[2][4][2], wl[2][4][2];
    #pragma unroll
    for (int nb = 0; nb < 2; nb++) {
        int jl = nb*8 + g;
        const float* wrow = Whh + (long)((jl>>2)*512 + cta*4 + (jl&3))*512 + w*64;
        #pragma unroll
        for (int c = 0; c < 4; c++) {
            float2 p0 = *(const float2*)(wrow + c*16 + 2*tq);
            float2 p1 = *(const float2*)(wrow + c*16 + 2*tq + 8);
            __nv_bfloat162 h0 = __floats2bfloat162_rn(p0.x, p0.y);
            __nv_bfloat162 h1 = __floats2bfloat162_rn(p1.x, p1.y);
            wh[nb][c][0] = *(unsigned*)&h0;
            wh[nb][c][1] = *(unsigned*)&h1;
            __nv_bfloat162 l0 = __floats2bfloat162_rn(
                p0.x - __bfloat162float(h0.x), p0.y - __bfloat162float(h0.y));
            __nv_bfloat162 l1 = __floats2bfloat162_rn(
                p1.x - __bfloat162float(h1.x), p1.y - __bfloat162float(h1.y));
            wl[nb][c][0] = *(unsigned*)&l0;
            wl[nb][c][1] = *(unsigned*)&l1;
        }
    }

    // flag base: all flags are equal at launch entry (monotonic across launches)
    unsigned base = g_flag[cta*FLAG_STRIDE];

    // zero h slot 0
    for (int i = cta*256 + tid; i < NB*DEC; i += LSTM_CTAS*256)
        g_hT[i] = 0.f;

    const int q   = tid >> 6;        // batch quad
    const int dl0 = tid & 63;
    const int jl_me = gate*4 + dl;   // this thread's j-local (0..15)
    float c_reg = 0.f;
    float h_out = 0.f;

    __syncthreads();
    if (tid == 0) st_rel(&g_flag[cta*FLAG_STRIDE], base + 1u);

    for (int t = 0; t < LSEQ; t++) {
        // wait: all 128 flags >= base+1+t (warp 0 polls, 4 flags per lane)
        if (tid < 32) {
            unsigned tgt = base + 1u + (unsigned)t;
            bool ok;
            do {
                ok = true;
                #pragma unroll
                for (int i = 0; i < 4; i++) {
                    unsigned v = ld_acq(&g_flag[(tid*4 + i)*FLAG_STRIDE]);
                    ok &= ((int)(v - tgt) >= 0);
                }
            } while (!__all_sync(0xffffffffu, ok));
        }
        __syncthreads();

        // prefetch xw (independent of h)
        float xwv = xw[(long)t*(G4*NB) + j*NB + b];

        // stage + split h(t): global [q][d][br] -> packed bf16 hi/lo planes [b][d/2]
        const float4* hsrc4 = (const float4*)(g_hT + (t & 1)*(NB*DEC));
        #pragma unroll
        for (int r = 0; r < 4; r++) {
            int d0 = r*128 + dl0*2;
            float4 va = __ldcg(hsrc4 + q*512 + d0);
            float4 vb = __ldcg(hsrc4 + q*512 + d0 + 1);
            int dp = d0 >> 1;
            #pragma unroll
            for (int i = 0; i < 4; i++) {
                float x0 = (i==0)?va.x:(i==1)?va.y:(i==2)?va.z:va.w;
                float x1 = (i==0)?vb.x:(i==1)?vb.y:(i==2)?vb.z:vb.w;
                __nv_bfloat162 hv = __floats2bfloat162_rn(x0, x1);
                __nv_bfloat162 lv = __floats2bfloat162_rn(
                    x0 - __bfloat162float(hv.x), x1 - __bfloat162float(hv.y));
                hiP[(4*q+i)*HP2 + dp] = *(unsigned*)&hv;
                loP[(4*q+i)*HP2 + dp] = *(unsigned*)&lv;
            }
        }
        __syncthreads();

        // bf16 tensor-core partial D[16b x 16jl] over this warp's k-slice (3-pass)
        float acc[2][2][4];
        #pragma unroll
        for (int nb = 0; nb < 2; nb++)
            #pragma unroll
            for (int p = 0; p < 2; p++)
                #pragma unroll
                for (int r = 0; r < 4; r++) acc[nb][p][r] = 0.f;

        #pragma unroll
        for (int c = 0; c < 4; c++) {
            int kb2 = (w*64 + c*16) >> 1;    // u32 index
            unsigned ah[4], al[4];
            ah[0] = hiP[g*HP2 + kb2 + tq];
            ah[1] = hiP[(g+8)*HP2 + kb2 + tq];
            ah[2] = hiP[g*HP2 + kb2 + tq + 4];
            ah[3] = hiP[(g+8)*HP2 + kb2 + tq + 4];
            al[0] = loP[g*HP2 + kb2 + tq];
            al[1] = loP[(g+8)*HP2 + kb2 + tq];
            al[2] = loP[g*HP2 + kb2 + tq + 4];
            al[3] = loP[(g+8)*HP2 + kb2 + tq + 4];
            int p = c & 1;
            #pragma unroll
            for (int nb = 0; nb < 2; nb++) {
                mma_bf16(acc[nb][p], ah, wh[nb][c]);
                mma_bf16(acc[nb][p], ah, wl[nb][c]);
                mma_bf16(acc[nb][p], al, wh[nb][c]);
            }
        }

        // write warp partials: rows g/g+8 (=b), cols nb*8+2tq(+1) (=jl), stride 17
        #pragma unroll
        for (int nb = 0; nb < 2; nb++) {
            int cbase = nb*8 + 2*tq;
            red[w*272 + g*17 + cbase]         = acc[nb][0][0] + acc[nb][1][0];
            red[w*272 + g*17 + cbase + 1]     = acc[nb][0][1] + acc[nb][1][1];
            red[w*272 + (g+8)*17 + cbase]     = acc[nb][0][2] + acc[nb][1][2];
            red[w*272 + (g+8)*17 + cbase + 1] = acc[nb][0][3] + acc[nb][1][3];
        }
        __syncthreads();

        // reduce 8 warps' partials + xw; all 256 threads do their own transcendental
        float s = xwv;
        #pragma unroll
        for (int ww = 0; ww < 8; ww++)
            s += red[ww*272 + b*17 + jl_me];
        gx[tid] = (gate == 2) ? tanhf(s) : sigf(s);
        __syncthreads();

        if (tid < 64) {
            float ig = gx[tid];
            float fg = gx[64 + tid];
            float gg = gx[128 + tid];
            float og = gx[192 + tid];
            c_reg = fg*c_reg + ig*gg;
            h_out = og * tanhf(c_reg);
            int ddl = tid >> 4, bb = tid & 15;
            // h -> transposed ring (4 contiguous 64B segments per CTA)
            asm volatile("st.global.cg.f32 [%0], %1;" ::
                "l"(&g_hT[(((t+1) & 1))*(NB*DEC)
                          + (bb >> 2)*2048 + cta*16 + ddl*4 + (bb & 3)]),
                "f"(h_out) : "memory");
            // producer-complete, then one release-store arrival
            asm volatile("bar.sync 1, 64;" ::: "memory");
            if (tid == 0) st_rel(&g_flag[cta*FLAG_STRIDE], base + 2u + (unsigned)t);
            // out store after arrival: off the critical path
            out[bb*bstr + (long)t*tstr + cta*4 + ddl] = h_out;
        }
    }
}

// ---------------- kernel 5: causal self-attention (CTA per (q,b)) ----------------
__global__ void __launch_bounds__(256) attn_kernel()
{
    __shared__ float hqs[512];
    __shared__ float sc[256];
    __shared__ float red[256];
    __shared__ float4 red4[256];
    int q = blockIdx.x, b = blockIdx.y;
    int tid = threadIdx.x;
    int nk = q + 1;
    float* catb = g_cat + (long)b*(LSEQ*2*DEC);

    if (tid < 128)
        ((float4*)hqs)[tid] = ((const float4*)(catb + q*1024 + 512))[tid];
    __syncthreads();

    int w = tid >> 5, lane = tid & 31;
    for (int k = w; k < nk; k += 8) {
        const float4* hk = (const float4*)(catb + k*1024 + 512);
        float s = 0.f;
        #pragma unroll
        for (int i = 0; i < 4; i++) {
            float4 a = ((float4*)hqs)[lane + 32*i];
            float4 c = hk[lane + 32*i];
            s += a.x*c.x + a.y*c.y + a.z*c.z + a.w*c.w;
        }
        #pragma unroll
        for (int off = 16; off; off >>= 1) s += __shfl_xor_sync(0xffffffffu, s, off);
        if (lane == 0) sc[k] = s;
    }
    __syncthreads();

    float v = (tid < nk) ? sc[tid] : -INFINITY;
    red[tid] = v; __syncthreads();
    #pragma unroll
    for (int s = 128; s; s >>= 1) {
        if (tid < s) red[tid] = fmaxf(red[tid], red[tid+s]);
        __syncthreads();
    }
    float mx = red[0]; __syncthreads();
    float e = (tid < nk) ? __expf(v - mx) : 0.f;
    red[tid] = e; __syncthreads();
    #pragma unroll
    for (int s = 128; s; s >>= 1) {
        if (tid < s) red[tid] += red[tid+s];
        __syncthreads();
    }
    float inv = 1.f / red[0];
    __syncthreads();
    if (tid < nk) sc[tid] = e * inv;
    __syncthreads();

    // mix: float4 per thread, 2 k-stripes
    int dq = tid & 127;
    int stripe = tid >> 7;
    float4 a = make_float4(0.f, 0.f, 0.f, 0.f);
    for (int k = stripe; k < nk; k += 2) {
        float wk = sc[k];
        float4 hv = *(const float4*)(catb + k*1024 + 512 + dq*4);
        a.x += wk*hv.x; a.y += wk*hv.y; a.z += wk*hv.z; a.w += wk*hv.w;
    }
    red4[tid] = a;
    __syncthreads();
    if (tid < 128) {
        float4 b0 = red4[tid], b1 = red4[tid+128];
        float4 r = make_float4(b0.x+b1.x, b0.y+b1.y, b0.z+b1.z, b0.w+b1.w);
        *(float4*)(catb + q*1024 + dq*4) = r;
    }
}

// ---------------- kernel 6: fc2 single-pass tf32 tensor GEMM (proven) ----------------
__global__ void __launch_bounds__(256, 2) fc2_tf32_kernel(
    const float* __restrict__ A, const float* __restrict__ B,
    const float* __restrict__ bias, float* __restrict__ C)
{
    extern __shared__ float smf[];
    const int tid  = threadIdx.x;
    const int lane = tid & 31;
    const int warp = tid >> 5;
    const int warp_m = warp >> 1;
    const int warp_n = warp & 1;
    const int m0 = blockIdx.y * 128;
    const int n0 = blockIdx.x * 128;
    const int g = lane >> 2;
    const int t = lane & 3;

    unsigned sbase = (unsigned)__cvta_generic_to_shared(smf);

    auto issue_load = [&](int buf, int k0) {
        #pragma unroll
        for (int rep = 0; rep < 8; rep++) {
            int i   = tid + rep*256;
            int mat = i >> 10;
            int idx = i & 1023;
            int row = idx >> 3;
            int q   = idx & 7;
            unsigned daddr = sbase + ((buf*2 + mat)*TF_TILE + row*TF_AST + q*4)*4;
            const float* gsrc = (mat ? B + (long)(n0+row)*DEC
                                     : A + (long)(m0+row)*DEC) + k0 + q*4;
            asm volatile("cp.async.cg.shared.global [%0], [%1], 16;\n"
                         :: "r"(daddr), "l"(gsrc));
        }
        asm volatile("cp.async.commit_group;\n");
    };

    float acc[2][8][4];
    #pragma unroll
    for (int i = 0; i < 2; i++)
        #pragma unroll
        for (int j = 0; j < 8; j++)
            #pragma unroll
            for (int r = 0; r < 4; r++) acc[i][j][r] = 0.f;

    issue_load(0, 0);

    int buf = 0;
    for (int ks = 0; ks < DEC/TF_KS; ks++) {
        asm volatile("cp.async.wait_group 0;\n");
        __syncthreads();
        if (ks + 1 < DEC/TF_KS) issue_load(buf ^ 1, (ks+1)*TF_KS);

        const float* sA = smf + (buf*2 + 0)*TF_TILE;
        const float* sB = smf + (buf*2 + 1)*TF_TILE;

        #pragma unroll
        for (int k8 = 0; k8 < 4; k8++) {
            int kc = k8*8 + t;
            unsigned af[2][4];
            #pragma unroll
            for (int im = 0; im < 2; im++) {
                int rb = warp_m*32 + im*16 + g;
                af[im][0] = f2tf32(sA[rb*TF_AST + kc]);
                af[im][1] = f2tf32(sA[(rb+8)*TF_AST + kc]);
                af[im][2] = f2tf32(sA[rb*TF_AST + kc + 4]);
                af[im][3] = f2tf32(sA[(rb+8)*TF_AST + kc + 4]);
            }
            unsigned bf[8][2];
            #pragma unroll
            for (int in = 0; in < 8; in++) {
                int nc = warp_n*64 + in*8 + g;
                bf[in][0] = f2tf32(sB[nc*TF_AST + kc]);
                bf[in][1] = f2tf32(sB[nc*TF_AST + kc + 4]);
            }
            #pragma unroll
            for (int im = 0; im < 2; im++)
                #pragma unroll
                for (int in = 0; in < 8; in++)
                    mma_tf32(acc[im][in], af[im], bf[in]);
        }
        buf ^= 1;
        __syncthreads();
    }

    #pragma unroll
    for (int im = 0; im < 2; im++) {
        int row = m0 + warp_m*32 + im*16 + g;
        #pragma unroll
        for (int in = 0; in < 8; in++) {
            int col = n0 + warp_n*64 + in*8 + t*2;
            float b0 = bias[col], b1 = bias[col+1];
            float2 v0 = make_float2(acc[im][in][0] + b0, acc[im][in][1] + b1);
            float2 v1 = make_float2(acc[im][in][2] + b0, acc[im][in][3] + b1);
            *(float2*)(C + (long)row*NV + col)     = v0;
            *(float2*)(C + (long)(row+8)*NV + col) = v1;
        }
    }
}

// ---------------- launch ----------------
extern "C" void kernel_launch(void* const* d_in, const int* in_sizes, int n_in,
                              void* d_out, int out_size)
{
    const float* x       = (const float*)d_in[0];
    const int*   y       = (const int*)  d_in[1];
    const float* fc1_w   = (const float*)d_in[2];
    const float* fc1_b   = (const float*)d_in[3];
    const float* bn_g    = (const float*)d_in[4];
    const float* bn_b    = (const float*)d_in[5];
    const float* emb     = (const float*)d_in[6];
    const float* l1_Wih  = (const float*)d_in[7];
    const float* l1_Whh  = (const float*)d_in[8];
    const float* l1_bih  = (const float*)d_in[9];
    const float* l1_bhh  = (const float*)d_in[10];
    const float* attn_W  = (const float*)d_in[11];
    const float* dc_Wih  = (const float*)d_in[12];
    const float* dc_Whh  = (const float*)d_in[13];
    const float* dc_bih  = (const float*)d_in[14];
    const float* dc_bhh  = (const float*)d_in[15];
    const float* fc2_w   = (const float*)d_in[16];
    const float* fc2_b   = (const float*)d_in[17];
    float* out = (float*)d_out;

    float *p_seq, *p_xw, *p_cat, *p_attn, *p_h2;
    cudaGetSymbolAddress((void**)&p_seq,  g_seq);
    cudaGetSymbolAddress((void**)&p_xw,   g_xw);
    cudaGetSymbolAddress((void**)&p_cat,  g_cat);
    cudaGetSymbolAddress((void**)&p_attn, g_attn);
    cudaGetSymbolAddress((void**)&p_h2,   g_h2);

    cudaFuncSetAttribute(lstm_kernel, cudaFuncAttributeMaxDynamicSharedMemorySize, LSTM_SMEM);
    cudaFuncSetAttribute(fc2_tf32_kernel, cudaFuncAttributeMaxDynamicSharedMemorySize, TF_SMEM);
    cudaFuncSetAttribute(gemm_tf32<1,false>, cudaFuncAttributeMaxDynamicSharedMemorySize, TF_SMEM);
    cudaFuncSetAttribute(gemm_tf32<0,true>,  cudaFuncAttributeMaxDynamicSharedMemorySize, TF_SMEM);

    // 1. fc1 + BN
    fc1_bn_kernel<<<1, 256>>>(x, fc1_w, fc1_b, bn_g, bn_b);
    // 2. embedding
    embed_kernel<<<NB*(LSEQ-1), 64>>>(y, emb);
    // 3. xw1 = seq @ l1_Wih^T + biases   (tf32, LSTM layout)
    gemm_tf32<1,false><<<dim3(G4/128, MROWS/128), 256, TF_SMEM>>>(
        p_seq, l1_Wih, l1_bih, l1_bhh, p_xw, G4, EMB, 0);
    // 4. LSTM 1  ->  g_cat[b][t][512:1024]
    lstm_kernel<<<LSTM_CTAS, 256, LSTM_SMEM>>>(
        p_xw, l1_Whh, p_cat + 512, (long)LSEQ*2*DEC, (long)2*DEC);
    // 5. attention -> g_cat[b][t][0:512]
    attn_kernel<<<dim3(LSEQ, NB), 256>>>();
    // 6. attn = tanh(cat @ attn_W^T)   (tf32)
    gemm_tf32<0,true><<<dim3(DEC/128, MROWS/128), 256, TF_SMEM>>>(
        p_cat, attn_W, nullptr, nullptr, p_attn, DEC, 2*DEC, DEC);
    // 7. xw2 = attn @ dc_Wih^T + biases (tf32, LSTM layout)
    gemm_tf32<1,false><<<dim3(G4/128, MROWS/128), 256, TF_SMEM>>>(
        p_attn, dc_Wih, dc_bih, dc_bhh, p_xw, G4, DEC, 0);
    // 8. LSTM 2 -> g_h2[m][d]
    lstm_kernel<<<LSTM_CTAS, 256, LSTM_SMEM>>>(
        p_xw, dc_Whh, p_h2, (long)LSEQ*DEC, (long)DEC);
    // 9. fc2 single-pass tf32 tensor GEMM -> d_out
    fc2_tf32_kernel<<<dim3(NV/128, MROWS/128), 256, TF_SMEM>>>(
        p_h2, fc2_w, fc2_b, out);
}

// round 17
// speedup vs baseline: 1.5340x; 1.4067x over previous
#include <cuda_runtime.h>
#include <cuda_bf16.h>
#include <math.h>

// ---------------- problem constants ----------------
#define NB   16          // batch
#define LSEQ 256         // sequence length (TY+1)
#define ENC  512
#define EMB  256
#define DEC  512
#define NV   32000
#define G4   2048        // 4*DEC
#define MROWS 4096       // NB*LSEQ

// ---------------- scratch (__device__ globals; no allocs) ----------------
__device__ float g_seq [NB*LSEQ*EMB];        //  4 MB  [b][t][EMB]
__device__ float g_xw  [LSEQ*G4*NB];         // 32 MB  [t][j][b]
__device__ float g_cat [NB*LSEQ*2*DEC];      // 16 MB  [b][t][ mix(512) | h1(512) ]
__device__ float g_attn[MROWS*DEC];          //  8 MB  [m][512]
__device__ float g_h2  [MROWS*DEC];          //  8 MB  [m][512]
// h double buffer, TRANSPOSED layout: word = q*2048 + d*4 + br  (b = 4q+br)
__device__ float g_hT  [2*NB*DEC];
// single monotonic barrier counter (reset to 0 by cta0 at end of each LSTM launch)
__device__ unsigned g_count;

__device__ __forceinline__ float sigf(float x){ return 1.0f/(1.0f+__expf(-x)); }

__device__ __forceinline__ unsigned ld_acq(const unsigned* p){
    unsigned v;
    asm volatile("ld.acquire.gpu.global.u32 %0, [%1];" : "=r"(v) : "l"(p) : "memory");
    return v;
}
__device__ __forceinline__ void red_rel(unsigned* p, unsigned v){
    asm volatile("red.release.gpu.global.add.u32 [%0], %1;"
                 :: "l"(p), "r"(v) : "memory");
}
__device__ __forceinline__ void st_rlx(unsigned* p, unsigned v){
    asm volatile("st.relaxed.gpu.global.u32 [%0], %1;" :: "l"(p), "r"(v) : "memory");
}

// ---------------- kernel 1: fc1 + BatchNorm (batch stats) -> seq[:,0,:] ----------------
__global__ void __launch_bounds__(256) fc1_bn_kernel(
    const float* __restrict__ x,     // [16,512]
    const float* __restrict__ w,     // [256,512]
    const float* __restrict__ bias,  // [256]
    const float* __restrict__ gam,   // [256]
    const float* __restrict__ bet)   // [256]
{
    __shared__ float xs[NB*ENC];     // 32 KB
    int tid = threadIdx.x;
    for (int i = tid; i < NB*ENC/4; i += 256)
        ((float4*)xs)[i] = ((const float4*)x)[i];
    __syncthreads();

    int j = tid;
    float f[NB];
    #pragma unroll
    for (int b = 0; b < NB; b++) f[b] = bias[j];

    const float4* w4 = (const float4*)(w + j*ENC);
    for (int k4 = 0; k4 < ENC/4; k4++) {
        float4 ww = w4[k4];
        #pragma unroll
        for (int b = 0; b < NB; b++) {
            float4 xx = ((float4*)xs)[b*(ENC/4) + k4];
            f[b] += ww.x*xx.x + ww.y*xx.y + ww.z*xx.z + ww.w*xx.w;
        }
    }
    float mu = 0.f;
    #pragma unroll
    for (int b = 0; b < NB; b++) mu += f[b];
    mu *= (1.0f/NB);
    float var = 0.f;
    #pragma unroll
    for (int b = 0; b < NB; b++) { float d = f[b]-mu; var += d*d; }
    var *= (1.0f/NB);
    float s = rsqrtf(var + 1e-5f) * gam[j];
    float bb = bet[j];
    #pragma unroll
    for (int b = 0; b < NB; b++)
        g_seq[b*(LSEQ*EMB) + j] = (f[b]-mu)*s + bb;   // t = 0
}

// ---------------- kernel 2: embedding gather -> seq[:,1:,:] ----------------
__global__ void embed_kernel(const int* __restrict__ y,      // [16,255]
                             const float* __restrict__ emb)  // [32000,256]
{
    int blk = blockIdx.x;
    int b = blk / (LSEQ-1), t = blk % (LSEQ-1);
    int row = y[b*(LSEQ-1) + t];
    const float4* src = (const float4*)(emb + (long)row*EMB);
    float4* dst = (float4*)(g_seq + b*(LSEQ*EMB) + (t+1)*EMB);
    dst[threadIdx.x] = src[threadIdx.x];
}

// ---------------- tf32/bf16 helpers ----------------
__device__ __forceinline__ unsigned f2tf32(float v)
{
    unsigned u;
    asm("cvt.rna.tf32.f32 %0, %1;" : "=r"(u) : "f"(v));
    return u;
}

__device__ __forceinline__ void mma_tf32(float* c, const unsigned* a, const unsigned* b)
{
    asm volatile(
        "mma.sync.aligned.m16n8k8.row.col.f32.tf32.tf32.f32 "
        "{%0,%1,%2,%3}, {%4,%5,%6,%7}, {%8,%9}, {%0,%1,%2,%3};\n"
        : "+f"(c[0]), "+f"(c[1]), "+f"(c[2]), "+f"(c[3])
        : "r"(a[0]), "r"(a[1]), "r"(a[2]), "r"(a[3]), "r"(b[0]), "r"(b[1]));
}

__device__ __forceinline__ void mma_bf16(float* c, const unsigned* a, const unsigned* b)
{
    asm volatile(
        "mma.sync.aligned.m16n8k16.row.col.f32.bf16.bf16.f32 "
        "{%0,%1,%2,%3}, {%4,%5,%6,%7}, {%8,%9}, {%0,%1,%2,%3};\n"
        : "+f"(c[0]), "+f"(c[1]), "+f"(c[2]), "+f"(c[3])
        : "r"(a[0]), "r"(a[1]), "r"(a[2]), "r"(a[3]), "r"(b[0]), "r"(b[1]));
}

#define TF_KS    32
#define TF_AST   36                        // smem row stride in floats (conflict-free)
#define TF_TILE  (128*TF_AST)              // floats per matrix tile
#define TF_SMEM  (2*2*TF_TILE*4)           // 73728 B

// ---------------- kernel 3: generic tf32 GEMM  C = A[M,K] * B[N,K]^T (+bias) ----------------
// MODE 0: C[m*Cld+n] (+tanh opt);  MODE 1: C[t*(N*16) + n*16 + b], m = b*256+t
template<int MODE, bool DOTANH>
__global__ void __launch_bounds__(256, 2) gemm_tf32(
    const float* __restrict__ A, const float* __restrict__ B,
    const float* __restrict__ bias0, const float* __restrict__ bias1,
    float* __restrict__ C, int N, int K, int Cld)
{
    extern __shared__ float smf[];
    const int tid  = threadIdx.x;
    const int lane = tid & 31;
    const int warp = tid >> 5;
    const int warp_m = warp >> 1;
    const int warp_n = warp & 1;
    const int m0 = blockIdx.y * 128;
    const int n0 = blockIdx.x * 128;
    const int g = lane >> 2;
    const int t = lane & 3;

    unsigned sbase = (unsigned)__cvta_generic_to_shared(smf);

    auto issue_load = [&](int buf, int k0) {
        #pragma unroll
        for (int rep = 0; rep < 8; rep++) {
            int i   = tid + rep*256;
            int mat = i >> 10;
            int idx = i & 1023;
            int row = idx >> 3;
            int q   = idx & 7;
            unsigned daddr = sbase + ((buf*2 + mat)*TF_TILE + row*TF_AST + q*4)*4;
            const float* gsrc = (mat ? B + (long)(n0+row)*K
                                     : A + (long)(m0+row)*K) + k0 + q*4;
            asm volatile("cp.async.cg.shared.global [%0], [%1], 16;\n"
                         :: "r"(daddr), "l"(gsrc));
        }
        asm volatile("cp.async.commit_group;\n");
    };

    float acc[2][8][4];
    #pragma unroll
    for (int i = 0; i < 2; i++)
        #pragma unroll
        for (int j = 0; j < 8; j++)
            #pragma unroll
            for (int r = 0; r < 4; r++) acc[i][j][r] = 0.f;

    issue_load(0, 0);

    int nst = K / TF_KS;
    int buf = 0;
    for (int ks = 0; ks < nst; ks++) {
        asm volatile("cp.async.wait_group 0;\n");
        __syncthreads();
        if (ks + 1 < nst) issue_load(buf ^ 1, (ks+1)*TF_KS);

        const float* sA = smf + (buf*2 + 0)*TF_TILE;
        const float* sB = smf + (buf*2 + 1)*TF_TILE;

        #pragma unroll
        for (int k8 = 0; k8 < 4; k8++) {
            int kc = k8*8 + t;
            unsigned af[2][4];
            #pragma unroll
            for (int im = 0; im < 2; im++) {
                int rb = warp_m*32 + im*16 + g;
                af[im][0] = f2tf32(sA[rb*TF_AST + kc]);
                af[im][1] = f2tf32(sA[(rb+8)*TF_AST + kc]);
                af[im][2] = f2tf32(sA[rb*TF_AST + kc + 4]);
                af[im][3] = f2tf32(sA[(rb+8)*TF_AST + kc + 4]);
            }
            unsigned bf[8][2];
            #pragma unroll
            for (int in = 0; in < 8; in++) {
                int nc = warp_n*64 + in*8 + g;
                bf[in][0] = f2tf32(sB[nc*TF_AST + kc]);
                bf[in][1] = f2tf32(sB[nc*TF_AST + kc + 4]);
            }
            #pragma unroll
            for (int im = 0; im < 2; im++)
                #pragma unroll
                for (int in = 0; in < 8; in++)
                    mma_tf32(acc[im][in], af[im], bf[in]);
        }
        buf ^= 1;
        __syncthreads();
    }

    #pragma unroll
    for (int im = 0; im < 2; im++) {
        int row = m0 + warp_m*32 + im*16 + g;
        #pragma unroll
        for (int in = 0; in < 8; in++) {
            int col = n0 + warp_n*64 + in*8 + t*2;
            float bs0 = 0.f, bs1 = 0.f;
            if (bias0) { bs0 += bias0[col]; bs1 += bias0[col+1]; }
            if (bias1) { bs0 += bias1[col]; bs1 += bias1[col+1]; }
            float v00 = acc[im][in][0] + bs0, v01 = acc[im][in][1] + bs1;
            float v10 = acc[im][in][2] + bs0, v11 = acc[im][in][3] + bs1;
            if (DOTANH) { v00 = tanhf(v00); v01 = tanhf(v01);
                          v10 = tanhf(v10); v11 = tanhf(v11); }
            if (MODE == 0) {
                *(float2*)(C + (long)row*Cld + col)     = make_float2(v00, v01);
                *(float2*)(C + (long)(row+8)*Cld + col) = make_float2(v10, v11);
            } else {
                int b0 = row >> 8, t0 = row & 255;
                int b1 = (row+8) >> 8, t1 = (row+8) & 255;
                C[(long)t0*(N*NB) + col*NB + b0]     = v00;
                C[(long)t0*(N*NB) + (col+1)*NB + b0] = v01;
                C[(long)t1*(N*NB) + col*NB + b1]     = v10;
                C[(long)t1*(N*NB) + (col+1)*NB + b1] = v11;
            }
        }
    }
}

// ---------------- kernel 4: persistent LSTM (128 CTAs, bf16 hi/lo tensor cores) ----------------
// R12 structure; barrier = fire-and-forget red.release to ONE monotonic counter
// + single-hot-word acquire polling (R12's proven poll pattern).
#define LSTM_CTAS 128
#define HP2  260                       // plane row stride (u32): bank = 4g+tq, bijective
#define SM_HI   0                      // 16*260 u32
#define SM_LO   4160                   // 16*260 u32
#define SM_GX   8320                   // 256 floats
#define SM_RED  8576                   // 8*272 floats
#define LSTM_SMEM ((8576 + 2176)*4)    // 43008 B

__global__ void __launch_bounds__(256, 1) lstm_kernel(
    const float* __restrict__ xw,
    const float* __restrict__ Whh,   // [2048,512]
    float* __restrict__ out, long bstr, long tstr)
{
    extern __shared__ unsigned smu[];
    unsigned* hiP = smu + SM_HI;
    unsigned* loP = smu + SM_LO;
    float*    gx  = (float*)(smu + SM_GX);
    float*    red = (float*)(smu + SM_RED);

    int tid = threadIdx.x, cta = blockIdx.x;
    int gate = tid >> 6, dl = (tid >> 4) & 3, b = tid & 15;
    int j  = gate*512 + cta*4 + dl;

    const int w    = tid >> 5;       // warp = k-slice owner
    const int lane = tid & 31;
    const int g    = lane >> 2;      // 0..7
    const int tq   = lane & 3;       // 0..3

    // --- preload W fragments (hi/lo bf16 packed pairs) for this warp's k-slice ---
    unsigned wh[2][4][2], wl[2][4][2];
    #pragma unroll
    for (int nb = 0; nb < 2; nb++) {
        int jl = nb*8 + g;
        const float* wrow = Whh + (long)((jl>>2)*512 + cta*4 + (jl&3))*512 + w*64;
        #pragma unroll
        for (int c = 0; c < 4; c++) {
            float2 p0 = *(const float2*)(wrow + c*16 + 2*tq);
            float2 p1 = *(const float2*)(wrow + c*16 + 2*tq + 8);
            __nv_bfloat162 h0 = __floats2bfloat162_rn(p0.x, p0.y);
            __nv_bfloat162 h1 = __floats2bfloat162_rn(p1.x, p1.y);
            wh[nb][c][0] = *(unsigned*)&h0;
            wh[nb][c][1] = *(unsigned*)&h1;
            __nv_bfloat162 l0 = __floats2bfloat162_rn(
                p0.x - __bfloat162float(h0.x), p0.y - __bfloat162float(h0.y));
            __nv_bfloat162 l1 = __floats2bfloat162_rn(
                p1.x - __bfloat162float(h1.x), p1.y - __bfloat162float(h1.y));
            wl[nb][c][0] = *(unsigned*)&l0;
            wl[nb][c][1] = *(unsigned*)&l1;
        }
    }

    // zero h slot 0
    for (int i = cta*256 + tid; i < NB*DEC; i += LSTM_CTAS*256)
        g_hT[i] = 0.f;

    const int q   = tid >> 6;        // batch quad
    const int dl0 = tid & 63;
    const int jl_me = gate*4 + dl;   // this thread's j-local (0..15)
    float c_reg = 0.f;
    float h_out = 0.f;

    // epoch 0 arrival: counter starts at 0 every launch (reset by previous user)
    __syncthreads();
    if (tid == 0) red_rel(&g_count, 1u);

    for (int t = 0; t < LSEQ; t++) {
        // wait: counter >= 128*(t+1)  (single hot word, tid0 polls)
        if (tid == 0) {
            unsigned tgt = 128u * (unsigned)(t + 1);
            while (ld_acq(&g_count) < tgt) { }
        }
        __syncthreads();

        // prefetch xw (independent of h)
        float xwv = xw[(long)t*(G4*NB) + j*NB + b];

        // stage + split h(t): global [q][d][br] -> packed bf16 hi/lo planes [b][d/2]
        const float4* hsrc4 = (const float4*)(g_hT + (t & 1)*(NB*DEC));
        #pragma unroll
        for (int r = 0; r < 4; r++) {
            int d0 = r*128 + dl0*2;
            float4 va = __ldcg(hsrc4 + q*512 + d0);
            float4 vb = __ldcg(hsrc4 + q*512 + d0 + 1);
            int dp = d0 >> 1;
            #pragma unroll
            for (int i = 0; i < 4; i++) {
                float x0 = (i==0)?va.x:(i==1)?va.y:(i==2)?va.z:va.w;
                float x1 = (i==0)?vb.x:(i==1)?vb.y:(i==2)?vb.z:vb.w;
                __nv_bfloat162 hv = __floats2bfloat162_rn(x0, x1);
                __nv_bfloat162 lv = __floats2bfloat162_rn(
                    x0 - __bfloat162float(hv.x), x1 - __bfloat162float(hv.y));
                hiP[(4*q+i)*HP2 + dp] = *(unsigned*)&hv;
                loP[(4*q+i)*HP2 + dp] = *(unsigned*)&lv;
            }
        }
        __syncthreads();

        // bf16 tensor-core partial D[16b x 16jl] over this warp's k-slice (3-pass)
        float acc[2][2][4];
        #pragma unroll
        for (int nb = 0; nb < 2; nb++)
            #pragma unroll
            for (int p = 0; p < 2; p++)
                #pragma unroll
                for (int r = 0; r < 4; r++) acc[nb][p][r] = 0.f;

        #pragma unroll
        for (int c = 0; c < 4; c++) {
            int kb2 = (w*64 + c*16) >> 1;    // u32 index
            unsigned ah[4], al[4];
            ah[0] = hiP[g*HP2 + kb2 + tq];
            ah[1] = hiP[(g+8)*HP2 + kb2 + tq];
            ah[2] = hiP[g*HP2 + kb2 + tq + 4];
            ah[3] = hiP[(g+8)*HP2 + kb2 + tq + 4];
            al[0] = loP[g*HP2 + kb2 + tq];
            al[1] = loP[(g+8)*HP2 + kb2 + tq];
            al[2] = loP[g*HP2 + kb2 + tq + 4];
            al[3] = loP[(g+8)*HP2 + kb2 + tq + 4];
            int p = c & 1;
            #pragma unroll
            for (int nb = 0; nb < 2; nb++) {
                mma_bf16(acc[nb][p], ah, wh[nb][c]);
                mma_bf16(acc[nb][p], ah, wl[nb][c]);
                mma_bf16(acc[nb][p], al, wh[nb][c]);
            }
        }

        // write warp partials: rows g/g+8 (=b), cols nb*8+2tq(+1) (=jl), stride 17
        #pragma unroll
        for (int nb = 0; nb < 2; nb++) {
            int cbase = nb*8 + 2*tq;
            red[w*272 + g*17 + cbase]         = acc[nb][0][0] + acc[nb][1][0];
            red[w*272 + g*17 + cbase + 1]     = acc[nb][0][1] + acc[nb][1][1];
            red[w*272 + (g+8)*17 + cbase]     = acc[nb][0][2] + acc[nb][1][2];
            red[w*272 + (g+8)*17 + cbase + 1] = acc[nb][0][3] + acc[nb][1][3];
        }
        __syncthreads();

        // reduce 8 warps' partials + xw; all 256 threads do their own transcendental
        float s = xwv;
        #pragma unroll
        for (int ww = 0; ww < 8; ww++)
            s += red[ww*272 + b*17 + jl_me];
        gx[tid] = (gate == 2) ? tanhf(s) : sigf(s);
        __syncthreads();

        if (tid < 64) {
            float ig = gx[tid];
            float fg = gx[64 + tid];
            float gg = gx[128 + tid];
            float og = gx[192 + tid];
            c_reg = fg*c_reg + ig*gg;
            h_out = og * tanhf(c_reg);
            int ddl = tid >> 4, bb = tid & 15;
            // h -> transposed ring (4 contiguous 64B segments per CTA)
            asm volatile("st.global.cg.f32 [%0], %1;" ::
                "l"(&g_hT[(((t+1) & 1))*(NB*DEC)
                          + (bb >> 2)*2048 + cta*16 + ddl*4 + (bb & 3)]),
                "f"(h_out) : "memory");
        }
        // order h-stores (CTA scope) before the release arrival
        __syncthreads();
        if (tid == 0 && t < LSEQ-1) red_rel(&g_count, 1u);
        // out store after arrival: off the release-ordered critical path
        if (tid < 64) {
            int ddl = tid >> 4, bb = tid & 15;
            out[bb*bstr + (long)t*tstr + cta*4 + ddl] = h_out;
        }
    }

    // "done polling" arrival, then cta0 resets the counter for the next launch
    if (tid == 0) {
        red_rel(&g_count, 1u);       // per-CTA total: 1 + 255 + 1 = 257
        if (cta == 0) {
            while (ld_acq(&g_count) < 128u*257u) { }
            st_rlx(&g_count, 0u);    // kernel exit publishes the reset
        }
    }
}

// ---------------- kernel 5: causal self-attention (CTA per (q,b)) ----------------
__global__ void __launch_bounds__(256) attn_kernel()
{
    __shared__ float hqs[512];
    __shared__ float sc[256];
    __shared__ float red[256];
    __shared__ float4 red4[256];
    int q = blockIdx.x, b = blockIdx.y;
    int tid = threadIdx.x;
    int nk = q + 1;
    float* catb = g_cat + (long)b*(LSEQ*2*DEC);

    if (tid < 128)
        ((float4*)hqs)[tid] = ((const float4*)(catb + q*1024 + 512))[tid];
    __syncthreads();

    int w = tid >> 5, lane = tid & 31;
    for (int k = w; k < nk; k += 8) {
        const float4* hk = (const float4*)(catb + k*1024 + 512);
        float s = 0.f;
        #pragma unroll
        for (int i = 0; i < 4; i++) {
            float4 a = ((float4*)hqs)[lane + 32*i];
            float4 c = hk[lane + 32*i];
            s += a.x*c.x + a.y*c.y + a.z*c.z + a.w*c.w;
        }
        #pragma unroll
        for (int off = 16; off; off >>= 1) s += __shfl_xor_sync(0xffffffffu, s, off);
        if (lane == 0) sc[k] = s;
    }
    __syncthreads();

    float v = (tid < nk) ? sc[tid] : -INFINITY;
    red[tid] = v; __syncthreads();
    #pragma unroll
    for (int s = 128; s; s >>= 1) {
        if (tid < s) red[tid] = fmaxf(red[tid], red[tid+s]);
        __syncthreads();
    }
    float mx = red[0]; __syncthreads();
    float e = (tid < nk) ? __expf(v - mx) : 0.f;
    red[tid] = e; __syncthreads();
    #pragma unroll
    for (int s = 128; s; s >>= 1) {
        if (tid < s) red[tid] += red[tid+s];
        __syncthreads();
    }
    float inv = 1.f / red[0];
    __syncthreads();
    if (tid < nk) sc[tid] = e * inv;
    __syncthreads();

    // mix: float4 per thread, 2 k-stripes
    int dq = tid & 127;
    int stripe = tid >> 7;
    float4 a = make_float4(0.f, 0.f, 0.f, 0.f);
    for (int k = stripe; k < nk; k += 2) {
        float wk = sc[k];
        float4 hv = *(const float4*)(catb + k*1024 + 512 + dq*4);
        a.x += wk*hv.x; a.y += wk*hv.y; a.z += wk*hv.z; a.w += wk*hv.w;
    }
    red4[tid] = a;
    __syncthreads();
    if (tid < 128) {
        float4 b0 = red4[tid], b1 = red4[tid+128];
        float4 r = make_float4(b0.x+b1.x, b0.y+b1.y, b0.z+b1.z, b0.w+b1.w);
        *(float4*)(catb + q*1024 + dq*4) = r;
    }
}

// ---------------- kernel 6: fc2 single-pass tf32 tensor GEMM (proven) ----------------
__global__ void __launch_bounds__(256, 2) fc2_tf32_kernel(
    const float* __restrict__ A, const float* __restrict__ B,
    const float* __restrict__ bias, float* __restrict__ C)
{
    extern __shared__ float smf[];
    const int tid  = threadIdx.x;
    const int lane = tid & 31;
    const int warp = tid >> 5;
    const int warp_m = warp >> 1;
    const int warp_n = warp & 1;
    const int m0 = blockIdx.y * 128;
    const int n0 = blockIdx.x * 128;
    const int g = lane >> 2;
    const int t = lane & 3;

    unsigned sbase = (unsigned)__cvta_generic_to_shared(smf);

    auto issue_load = [&](int buf, int k0) {
        #pragma unroll
        for (int rep = 0; rep < 8; rep++) {
            int i   = tid + rep*256;
            int mat = i >> 10;
            int idx = i & 1023;
            int row = idx >> 3;
            int q   = idx & 7;
            unsigned daddr = sbase + ((buf*2 + mat)*TF_TILE + row*TF_AST + q*4)*4;
            const float* gsrc = (mat ? B + (long)(n0+row)*DEC
                                     : A + (long)(m0+row)*DEC) + k0 + q*4;
            asm volatile("cp.async.cg.shared.global [%0], [%1], 16;\n"
                         :: "r"(daddr), "l"(gsrc));
        }
        asm volatile("cp.async.commit_group;\n");
    };

    float acc[2][8][4];
    #pragma unroll
    for (int i = 0; i < 2; i++)
        #pragma unroll
        for (int j = 0; j < 8; j++)
            #pragma unroll
            for (int r = 0; r < 4; r++) acc[i][j][r] = 0.f;

    issue_load(0, 0);

    int buf = 0;
    for (int ks = 0; ks < DEC/TF_KS; ks++) {
        asm volatile("cp.async.wait_group 0;\n");
        __syncthreads();
        if (ks + 1 < DEC/TF_KS) issue_load(buf ^ 1, (ks+1)*TF_KS);

        const float* sA = smf + (buf*2 + 0)*TF_TILE;
        const float* sB = smf + (buf*2 + 1)*TF_TILE;

        #pragma unroll
        for (int k8 = 0; k8 < 4; k8++) {
            int kc = k8*8 + t;
            unsigned af[2][4];
            #pragma unroll
            for (int im = 0; im < 2; im++) {
                int rb = warp_m*32 + im*16 + g;
                af[im][0] = f2tf32(sA[rb*TF_AST + kc]);
                af[im][1] = f2tf32(sA[(rb+8)*TF_AST + kc]);
                af[im][2] = f2tf32(sA[rb*TF_AST + kc + 4]);
                af[im][3] = f2tf32(sA[(rb+8)*TF_AST + kc + 4]);
            }
            unsigned bf[8][2];
            #pragma unroll
            for (int in = 0; in < 8; in++) {
                int nc = warp_n*64 + in*8 + g;
                bf[in][0] = f2tf32(sB[nc*TF_AST + kc]);
                bf[in][1] = f2tf32(sB[nc*TF_AST + kc + 4]);
            }
            #pragma unroll
            for (int im = 0; im < 2; im++)
                #pragma unroll
                for (int in = 0; in < 8; in++)
                    mma_tf32(acc[im][in], af[im], bf[in]);
        }
        buf ^= 1;
        __syncthreads();
    }

    #pragma unroll
    for (int im = 0; im < 2; im++) {
        int row = m0 + warp_m*32 + im*16 + g;
        #pragma unroll
        for (int in = 0; in < 8; in++) {
            int col = n0 + warp_n*64 + in*8 + t*2;
            float b0 = bias[col], b1 = bias[col+1];
            float2 v0 = make_float2(acc[im][in][0] + b0, acc[im][in][1] + b1);
            float2 v1 = make_float2(acc[im][in][2] + b0, acc[im][in][3] + b1);
            *(float2*)(C + (long)row*NV + col)     = v0;
            *(float2*)(C + (long)(row+8)*NV + col) = v1;
        }
    }
}

// ---------------- launch ----------------
extern "C" void kernel_launch(void* const* d_in, const int* in_sizes, int n_in,
                              void* d_out, int out_size)
{
    const float* x       = (const float*)d_in[0];
    const int*   y       = (const int*)  d_in[1];
    const float* fc1_w   = (const float*)d_in[2];
    const float* fc1_b   = (const float*)d_in[3];
    const float* bn_g    = (const float*)d_in[4];
    const float* bn_b    = (const float*)d_in[5];
    const float* emb     = (const float*)d_in[6];
    const float* l1_Wih  = (const float*)d_in[7];
    const float* l1_Whh  = (const float*)d_in[8];
    const float* l1_bih  = (const float*)d_in[9];
    const float* l1_bhh  = (const float*)d_in[10];
    const float* attn_W  = (const float*)d_in[11];
    const float* dc_Wih  = (const float*)d_in[12];
    const float* dc_Whh  = (const float*)d_in[13];
    const float* dc_bih  = (const float*)d_in[14];
    const float* dc_bhh  = (const float*)d_in[15];
    const float* fc2_w   = (const float*)d_in[16];
    const float* fc2_b   = (const float*)d_in[17];
    float* out = (float*)d_out;

    float *p_seq, *p_xw, *p_cat, *p_attn, *p_h2;
    cudaGetSymbolAddress((void**)&p_seq,  g_seq);
    cudaGetSymbolAddress((void**)&p_xw,   g_xw);
    cudaGetSymbolAddress((void**)&p_cat,  g_cat);
    cudaGetSymbolAddress((void**)&p_attn, g_attn);
    cudaGetSymbolAddress((void**)&p_h2,   g_h2);

    cudaFuncSetAttribute(lstm_kernel, cudaFuncAttributeMaxDynamicSharedMemorySize, LSTM_SMEM);
    cudaFuncSetAttribute(fc2_tf32_kernel, cudaFuncAttributeMaxDynamicSharedMemorySize, TF_SMEM);
    cudaFuncSetAttribute(gemm_tf32<1,false>, cudaFuncAttributeMaxDynamicSharedMemorySize, TF_SMEM);
    cudaFuncSetAttribute(gemm_tf32<0,true>,  cudaFuncAttributeMaxDynamicSharedMemorySize, TF_SMEM);

    // 1. fc1 + BN
    fc1_bn_kernel<<<1, 256>>>(x, fc1_w, fc1_b, bn_g, bn_b);
    // 2. embedding
    embed_kernel<<<NB*(LSEQ-1), 64>>>(y, emb);
    // 3. xw1 = seq @ l1_Wih^T + biases   (tf32, LSTM layout)
    gemm_tf32<1,false><<<dim3(G4/128, MROWS/128), 256, TF_SMEM>>>(
        p_seq, l1_Wih, l1_bih, l1_bhh, p_xw, G4, EMB, 0);
    // 4. LSTM 1  ->  g_cat[b][t][512:1024]
    lstm_kernel<<<LSTM_CTAS, 256, LSTM_SMEM>>>(
        p_xw, l1_Whh, p_cat + 512, (long)LSEQ*2*DEC, (long)2*DEC);
    // 5. attention -> g_cat[b][t][0:512]
    attn_kernel<<<dim3(LSEQ, NB), 256>>>();
    // 6. attn = tanh(cat @ attn_W^T)   (tf32)
    gemm_tf32<0,true><<<dim3(DEC/128, MROWS/128), 256, TF_SMEM>>>(
        p_cat, attn_W, nullptr, nullptr, p_attn, DEC, 2*DEC, DEC);
    // 7. xw2 = attn @ dc_Wih^T + biases (tf32, LSTM layout)
    gemm_tf32<1,false><<<dim3(G4/128, MROWS/128), 256, TF_SMEM>>>(
        p_attn, dc_Wih, dc_bih, dc_bhh, p_xw, G4, DEC, 0);
    // 8. LSTM 2 -> g_h2[m][d]
    lstm_kernel<<<LSTM_CTAS, 256, LSTM_SMEM>>>(
        p_xw, dc_Whh, p_h2, (long)LSEQ*DEC, (long)DEC);
    // 9. fc2 single-pass tf32 tensor GEMM -> d_out
    fc2_tf32_kernel<<<dim3(NV/128, MROWS/128), 256, TF_SMEM>>>(
        p_h2, fc2_w, fc2_b, out);
}